// round 16
// baseline (speedup 1.0000x reference)
#include <cuda_runtime.h>
#include <cuda_bf16.h>
#include <cstdint>

// Problem dims
#define EMBED 512
#define FFN   64
#define NQ    16
#define NTOK  65536   // 16 * 4096

// GEMM tiling: CTA 128 threads, tile 128 tok x 128 e, warp tile 64x64
#define MT 128
#define NT 128
#define BSTRIDE 272         // B smem row stride bytes (256B data + 16B pad)
#define ZSTRIDE 80          // z tile row stride (64B data + 16B pad)
#define W1STRIDE 80

// smem offsets (H is register-resident; no A tile)
#define OFF_B   0                     // 128 * 272 = 34816
#define OFF_Z   34816                 // 128 * 80  = 10240
#define OFF_W1  45056                 // 64 * 80   = 5120
#define OFF_B1  50176                 // 64 floats = 256
#define OFF_B2  50432                 // 128 floats = 512
#define SMEM_TOTAL 50944

// W2, bf16 two-term split, sigma-permuted slot order: slot g holds row
// (g&~63)|sigma(g&63), data = [Wh(64 bf16) | Wl(64 bf16)] = 256B.
__device__ __align__(16) __nv_bfloat16 g_w2b[(size_t)EMBED * 128];

// sigma forward: s=(b5 b4 b3 b2 b1 b0) -> (b5 b4 b2 b1 b3 b0)
__device__ __forceinline__ int sigma_fwd(int s) {
    return 16 * (s >> 4) + 4 * ((s & 7) >> 1) + 2 * ((s >> 3) & 1) + (s & 1);
}

__device__ __forceinline__ uint32_t smem_u32(const void* p) {
    uint32_t a;
    asm("{ .reg .u64 t; cvta.to.shared.u64 t, %1; cvt.u32.u64 %0, t; }"
        : "=r"(a) : "l"(p));
    return a;
}

#define LDSM_X4(r0, r1, r2, r3, addr) \
    asm volatile("ldmatrix.sync.aligned.m8n8.x4.shared.b16 {%0,%1,%2,%3}, [%4];" \
                 : "=r"(r0), "=r"(r1), "=r"(r2), "=r"(r3) : "r"(addr))

#define MMA16816(d, a0, a1, a2, a3, b0, b1) \
    asm volatile("mma.sync.aligned.m16n8k16.row.col.f32.bf16.bf16.f32 " \
                 "{%0,%1,%2,%3}, {%4,%5,%6,%7}, {%8,%9}, {%0,%1,%2,%3};" \
                 : "+f"((d)[0]), "+f"((d)[1]), "+f"((d)[2]), "+f"((d)[3]) \
                 : "r"(a0), "r"(a1), "r"(a2), "r"(a3), "r"(b0), "r"(b1))

// Exact truncation split: v = hi + lo; hi = bf16-trunc(v); lo exactly bf16.
__device__ __forceinline__ void trunc_split2(float v0, float v1,
                                             uint32_t& hi, uint32_t& lo) {
    uint32_t u0 = __float_as_uint(v0), u1 = __float_as_uint(v1);
    float h0 = __uint_as_float(u0 & 0xFFFF0000u);
    float h1 = __uint_as_float(u1 & 0xFFFF0000u);
    float l0 = v0 - h0, l1 = v1 - h1;       // exact (Dekker truncation)
    asm("prmt.b32 %0, %1, %2, 0x7632;" : "=r"(hi) : "r"(u0), "r"(u1));
    asm("prmt.b32 %0, %1, %2, 0x7632;" : "=r"(lo)
        : "r"(__float_as_uint(l0)), "r"(__float_as_uint(l1)));
}

// ---------------------------------------------------------------------------
// Prep kernel: sigma-permuted bf16 split of W2 (one thread per slot).
// ---------------------------------------------------------------------------
__global__ void __launch_bounds__(256) w2_prep(const float* __restrict__ W2)
{
    int g = blockIdx.x * 256 + threadIdx.x;          // slot in [0, 512)
    int src = (g & ~63) | sigma_fwd(g & 63);
    const float4* wp = (const float4*)(W2 + (size_t)src * FFN);
    float4 v[16];
#pragma unroll
    for (int i = 0; i < 16; i++) v[i] = wp[i];
    uint32_t hi[32], lo[32];
#pragma unroll
    for (int i = 0; i < 16; i++) {
        trunc_split2(v[i].x, v[i].y, hi[2*i],   lo[2*i]);
        trunc_split2(v[i].z, v[i].w, hi[2*i+1], lo[2*i+1]);
    }
    uint4* dst = (uint4*)(g_w2b + (size_t)g * 128);
#pragma unroll
    for (int i = 0; i < 8; i++)
        dst[i] = make_uint4(hi[4*i], hi[4*i+1], hi[4*i+2], hi[4*i+3]);
#pragma unroll
    for (int i = 0; i < 8; i++)
        dst[8 + i] = make_uint4(lo[4*i], lo[4*i+1], lo[4*i+2], lo[4*i+3]);
}

// ---------------------------------------------------------------------------
// Fused kernel, register-resident H, 64x64 warp tiles (4 warps, 255-reg budget).
// ---------------------------------------------------------------------------
__global__ void __launch_bounds__(128, 2) fused_ffn(
    const float* __restrict__ x,
    const float* __restrict__ theta,
    const float* __restrict__ W1,
    const float* __restrict__ b1,
    const float* __restrict__ b2,
    float* __restrict__ out)
{
    extern __shared__ char dsm[];
    char*  sB  = dsm + OFF_B;
    char*  sZ  = dsm + OFF_Z;
    char*  sW1 = dsm + OFF_W1;
    float* b1s = (float*)(dsm + OFF_B1);
    float* b2s = (float*)(dsm + OFF_B2);

    uint32_t sBu  = smem_u32(sB);
    uint32_t sZu  = smem_u32(sZ);
    uint32_t sW1u = smem_u32(sW1);

    int tid = threadIdx.x;
    int e0  = blockIdx.x * NT;
    int gt0 = blockIdx.y * MT;

    // ---------------- Phase 0/1: loads + splits into smem ----------------
    // z: one thread per token row (all 16 q-features)
    {
        const float4* xp = (const float4*)(x + (size_t)(gt0 + tid) * EMBED);
        float4 xv[4];
#pragma unroll
        for (int i = 0; i < 4; i++) xv[i] = xp[i];
        float zf[16];
        const float* xf = (const float*)xv;
#pragma unroll
        for (int j = 0; j < 16; j++)
            zf[j] = __cosf(xf[j]) * __cosf(theta[j]);
        uint32_t hi[8], lo[8];
#pragma unroll
        for (int j = 0; j < 8; j++)
            trunc_split2(zf[2*j], zf[2*j+1], hi[j], lo[j]);
        char* zr = sZ + tid * ZSTRIDE;
        *(uint4*)(zr)      = make_uint4(hi[0], hi[1], hi[2], hi[3]);
        *(uint4*)(zr + 16) = make_uint4(hi[4], hi[5], hi[6], hi[7]);
        *(uint4*)(zr + 32) = make_uint4(lo[0], lo[1], lo[2], lo[3]);
        *(uint4*)(zr + 48) = make_uint4(lo[4], lo[5], lo[6], lo[7]);
    }
    // W1: 2 threads per row (8 floats each)
    {
        int row = tid >> 1, q = tid & 1;
        const float4* wp = (const float4*)(W1 + (size_t)row * NQ + q * 8);
        float4 va = wp[0], vb = wp[1];
        uint32_t h[4], l[4];
        trunc_split2(va.x, va.y, h[0], l[0]);
        trunc_split2(va.z, va.w, h[1], l[1]);
        trunc_split2(vb.x, vb.y, h[2], l[2]);
        trunc_split2(vb.z, vb.w, h[3], l[3]);
        char* rb = sW1 + row * W1STRIDE + q * 16;
        *(uint4*)(rb)      = make_uint4(h[0], h[1], h[2], h[3]);
        *(uint4*)(rb + 32) = make_uint4(l[0], l[1], l[2], l[3]);
    }
    // W2: straight copy from pre-split, pre-permuted g_w2b (coalesced 256B/thread)
    {
        const uint4* src = (const uint4*)(g_w2b + (size_t)(e0 + tid) * 128);
        uint4* dst = (uint4*)(sB + tid * BSTRIDE);
        uint4 v[16];
#pragma unroll
        for (int i = 0; i < 16; i++) v[i] = src[i];
#pragma unroll
        for (int i = 0; i < 16; i++) dst[i] = v[i];
    }
    if (tid < FFN) b1s[tid] = b1[tid];
    b2s[tid] = b2[e0 + tid];
    __syncthreads();

    int wid = tid >> 5, l = tid & 31;
    int wm = wid & 1;        // M block (64 token rows)
    int wn = wid >> 1;       // N block (64 e cols)
    int c  = l & 3;

    // ---------------- Pre-loop: z fragments + output accumulators ----------------
    uint32_t zh[4][4], zl[4][4];
    {
        uint32_t zBase = sZu + (uint32_t)(wm * 64 + (l & 15)) * ZSTRIDE + ((l >> 4) << 4);
#pragma unroll
        for (int mt = 0; mt < 4; mt++) {
            LDSM_X4(zh[mt][0], zh[mt][1], zh[mt][2], zh[mt][3],
                    zBase + (uint32_t)(mt * 16) * ZSTRIDE);
            LDSM_X4(zl[mt][0], zl[mt][1], zl[mt][2], zl[mt][3],
                    zBase + (uint32_t)(mt * 16) * ZSTRIDE + 32);
        }
    }

    float acc[4][8][4];
    {
        int cb = wn * 64;
#pragma unroll
        for (int nt = 0; nt < 8; nt++) {
            int col = cb + 16 * (nt >> 1) + 4 * c + 2 * (nt & 1);
            float bv0 = b2s[col];
            float bv1 = b2s[col + 1];
#pragma unroll
            for (int mt = 0; mt < 4; mt++) {
                acc[mt][nt][0] = bv0; acc[mt][nt][1] = bv1;
                acc[mt][nt][2] = bv0; acc[mt][nt][3] = bv1;
            }
        }
    }

    uint32_t w1Base = sW1u + (uint32_t)((l & 7) + ((l >> 4) << 3)) * W1STRIDE
                           + (((l >> 3) & 1) << 4);
    uint32_t bRow  = (uint32_t)(wn * 64 + (l & 7) + ((l >> 4) << 3));
    uint32_t bBase = sBu + bRow * BSTRIDE + (((l >> 3) & 1) << 4);

    // ---------------- Main loop: 4 chunks of 16 FFN cols ----------------
#pragma unroll
    for (int kin = 0; kin < 4; kin++) {
        uint32_t kb = (uint32_t)(kin * 32);

        // bh issued FIRST: its LDS latency hides behind the H MMAs below.
        uint32_t bh[8][2];
#pragma unroll
        for (int j = 0; j < 4; j++) {
            uint32_t r0, r1, r2, r3;
            LDSM_X4(r0, r1, r2, r3, bBase + (uint32_t)(j * 16) * BSTRIDE + kb);
            bh[2*j][0] = r0;  bh[2*j][1] = r1;
            bh[2*j+1][0] = r2; bh[2*j+1][1] = r3;
        }

        // --- H chunk: rows wm*64..+64, cols kin*16..+16, 3-term MMA ---
        uint32_t ah[4][4], al[4][4];
        {
            uint32_t w1k = w1Base + (uint32_t)(kin * 16) * W1STRIDE;
            uint32_t w1h[2][2], w1l[2][2];
            {
                uint32_t r0, r1, r2, r3;
                LDSM_X4(r0, r1, r2, r3, w1k);
                w1h[0][0] = r0; w1h[0][1] = r1; w1h[1][0] = r2; w1h[1][1] = r3;
                LDSM_X4(r0, r1, r2, r3, w1k + 32);
                w1l[0][0] = r0; w1l[0][1] = r1; w1l[1][0] = r2; w1l[1][1] = r3;
            }

            float hacc[4][2][4];
#pragma unroll
            for (int nt = 0; nt < 2; nt++) {
                int f = kin * 16 + nt * 8 + c * 2;
                float bv0 = b1s[f], bv1 = b1s[f + 1];
#pragma unroll
                for (int mt = 0; mt < 4; mt++) {
                    hacc[mt][nt][0] = bv0; hacc[mt][nt][1] = bv1;
                    hacc[mt][nt][2] = bv0; hacc[mt][nt][3] = bv1;
                }
            }

#pragma unroll
            for (int mt = 0; mt < 4; mt++)
#pragma unroll
                for (int nt = 0; nt < 2; nt++) {
                    MMA16816(hacc[mt][nt], zh[mt][0], zh[mt][1], zh[mt][2], zh[mt][3],
                             w1h[nt][0], w1h[nt][1]);
                    MMA16816(hacc[mt][nt], zh[mt][0], zh[mt][1], zh[mt][2], zh[mt][3],
                             w1l[nt][0], w1l[nt][1]);
                    MMA16816(hacc[mt][nt], zl[mt][0], zl[mt][1], zl[mt][2], zl[mt][3],
                             w1h[nt][0], w1h[nt][1]);
                }

            // relu + split + PRMT: C fragments -> A fragments (registers)
#pragma unroll
            for (int mt = 0; mt < 4; mt++) {
                float v0 = fmaxf(hacc[mt][0][0], 0.0f);
                float v1 = fmaxf(hacc[mt][0][1], 0.0f);
                float v2 = fmaxf(hacc[mt][0][2], 0.0f);
                float v3 = fmaxf(hacc[mt][0][3], 0.0f);
                float v4 = fmaxf(hacc[mt][1][0], 0.0f);
                float v5 = fmaxf(hacc[mt][1][1], 0.0f);
                float v6 = fmaxf(hacc[mt][1][2], 0.0f);
                float v7 = fmaxf(hacc[mt][1][3], 0.0f);
                trunc_split2(v0, v1, ah[mt][0], al[mt][0]);   // rows g,   k0-7
                trunc_split2(v2, v3, ah[mt][1], al[mt][1]);   // rows g+8, k0-7
                trunc_split2(v4, v5, ah[mt][2], al[mt][2]);   // rows g,   k8-15
                trunc_split2(v6, v7, ah[mt][3], al[mt][3]);   // rows g+8, k8-15
            }
        }

        // term 0: Hh * Wh
#pragma unroll
        for (int mt = 0; mt < 4; mt++)
#pragma unroll
            for (int nt = 0; nt < 8; nt++)
                MMA16816(acc[mt][nt], ah[mt][0], ah[mt][1], ah[mt][2], ah[mt][3],
                         bh[nt][0], bh[nt][1]);

        uint32_t bl[8][2];
#pragma unroll
        for (int j = 0; j < 4; j++) {
            uint32_t r0, r1, r2, r3;
            LDSM_X4(r0, r1, r2, r3, bBase + (uint32_t)(j * 16) * BSTRIDE + 128 + kb);
            bl[2*j][0] = r0;  bl[2*j][1] = r1;
            bl[2*j+1][0] = r2; bl[2*j+1][1] = r3;
        }

        // term 2: Hl * Wh
#pragma unroll
        for (int mt = 0; mt < 4; mt++)
#pragma unroll
            for (int nt = 0; nt < 8; nt++)
                MMA16816(acc[mt][nt], al[mt][0], al[mt][1], al[mt][2], al[mt][3],
                         bh[nt][0], bh[nt][1]);

        // term 1: Hh * Wl
#pragma unroll
        for (int mt = 0; mt < 4; mt++)
#pragma unroll
            for (int nt = 0; nt < 8; nt++)
                MMA16816(acc[mt][nt], ah[mt][0], ah[mt][1], ah[mt][2], ah[mt][3],
                         bl[nt][0], bl[nt][1]);
    }

    // ---------------- Epilogue: sigma layout -> contiguous float4 ----------------
    {
        int row_l = l >> 2;
#pragma unroll
        for (int mt = 0; mt < 4; mt++) {
            int r0 = gt0 + wm * 64 + mt * 16 + row_l;
            float* base0 = out + (size_t)r0 * EMBED + e0 + wn * 64;
            float* base1 = base0 + (size_t)8 * EMBED;
#pragma unroll
            for (int g = 0; g < 4; g++) {
                float4 v0, v1;
                v0.x = acc[mt][2*g][0];   v0.y = acc[mt][2*g][1];
                v0.z = acc[mt][2*g+1][0]; v0.w = acc[mt][2*g+1][1];
                v1.x = acc[mt][2*g][2];   v1.y = acc[mt][2*g][3];
                v1.z = acc[mt][2*g+1][2]; v1.w = acc[mt][2*g+1][3];
                *(float4*)(base0 + 16 * g + 4 * c) = v0;
                *(float4*)(base1 + 16 * g + 4 * c) = v1;
            }
        }
    }
}

// ---------------------------------------------------------------------------
extern "C" void kernel_launch(void* const* d_in, const int* in_sizes, int n_in,
                              void* d_out, int out_size)
{
    const float *x = nullptr, *theta = nullptr, *W1 = nullptr,
                *b1 = nullptr, *W2 = nullptr, *b2 = nullptr;
    for (int i = 0; i < n_in; i++) {
        switch (in_sizes[i]) {
            case NTOK * EMBED: x     = (const float*)d_in[i]; break;
            case NQ:           theta = (const float*)d_in[i]; break;
            case FFN * NQ:     W1    = (const float*)d_in[i]; break;
            case FFN:          b1    = (const float*)d_in[i]; break;
            case EMBED * FFN:  W2    = (const float*)d_in[i]; break;
            case EMBED:        b2    = (const float*)d_in[i]; break;
            default: break;
        }
    }
    float* out = (float*)d_out;

    static int smem_set = 0;
    if (!smem_set) {
        cudaFuncSetAttribute(fused_ffn,
                             cudaFuncAttributeMaxDynamicSharedMemorySize,
                             SMEM_TOTAL);
        smem_set = 1;
    }

    w2_prep<<<2, 256>>>(W2);
    fused_ffn<<<dim3(EMBED / NT, NTOK / MT), 128, SMEM_TOTAL>>>(
        x, theta, W1, b1, b2, out);
}

// round 17
// speedup vs baseline: 1.0999x; 1.0999x over previous
#include <cuda_runtime.h>
#include <cuda_bf16.h>
#include <cstdint>

// Problem dims
#define EMBED 512
#define FFN   64
#define NQ    16
#define NTOK  65536   // 16 * 4096

// GEMM tiling: CTA 128 threads, tile 128 tok x 128 e, warp tile 64x64
#define MT 128
#define NT 128
#define BSTRIDE 272         // B smem row stride bytes (256B data + 16B pad)
#define ZSTRIDE 80          // z tile row stride (64B data + 16B pad)
#define W1STRIDE 80

// smem offsets (H is register-resident; no A tile)
#define OFF_B   0                     // 128 * 272 = 34816
#define OFF_Z   34816                 // 128 * 80  = 10240
#define OFF_W1  45056                 // 64 * 80   = 5120
#define OFF_B1  50176                 // 64 floats = 256
#define OFF_B2  50432                 // 128 floats = 512
#define SMEM_TOTAL 50944

// sigma: within a 64-col group, slot s holds W2 row sigma(s):
// s=(b5 b4 b3 b2 b1 b0) -> phys=(b5 b4 b2 b1 b3 b0)
__device__ __forceinline__ int sigma_inv(int p) {
    // inverse: (p5 p4 p3 p2 p1 p0) -> (p5 p4 p1 p3 p2 p0)
    return 16 * (p >> 4) + 8 * ((p >> 1) & 1) + 2 * ((p >> 2) & 3) + (p & 1);
}

__device__ __forceinline__ uint32_t smem_u32(const void* p) {
    uint32_t a;
    asm("{ .reg .u64 t; cvta.to.shared.u64 t, %1; cvt.u32.u64 %0, t; }"
        : "=r"(a) : "l"(p));
    return a;
}

#define LDSM_X4(r0, r1, r2, r3, addr) \
    asm volatile("ldmatrix.sync.aligned.m8n8.x4.shared.b16 {%0,%1,%2,%3}, [%4];" \
                 : "=r"(r0), "=r"(r1), "=r"(r2), "=r"(r3) : "r"(addr))

#define MMA16816(d, a0, a1, a2, a3, b0, b1) \
    asm volatile("mma.sync.aligned.m16n8k16.row.col.f32.bf16.bf16.f32 " \
                 "{%0,%1,%2,%3}, {%4,%5,%6,%7}, {%8,%9}, {%0,%1,%2,%3};" \
                 : "+f"((d)[0]), "+f"((d)[1]), "+f"((d)[2]), "+f"((d)[3]) \
                 : "r"(a0), "r"(a1), "r"(a2), "r"(a3), "r"(b0), "r"(b1))

// Exact truncation split: v = hi + lo; hi = bf16-trunc(v); lo exactly bf16.
__device__ __forceinline__ void trunc_split2(float v0, float v1,
                                             uint32_t& hi, uint32_t& lo) {
    uint32_t u0 = __float_as_uint(v0), u1 = __float_as_uint(v1);
    float h0 = __uint_as_float(u0 & 0xFFFF0000u);
    float h1 = __uint_as_float(u1 & 0xFFFF0000u);
    float l0 = v0 - h0, l1 = v1 - h1;       // exact (Dekker truncation)
    asm("prmt.b32 %0, %1, %2, 0x7632;" : "=r"(hi) : "r"(u0), "r"(u1));
    asm("prmt.b32 %0, %1, %2, 0x7632;" : "=r"(lo)
        : "r"(__float_as_uint(l0)), "r"(__float_as_uint(l1)));
}

// ---------------------------------------------------------------------------
// Fused kernel, register-resident H, 64x64 warp tiles, software-pipelined:
// the H chunk for kin+1 is computed between the main MMA bursts of kin.
// ---------------------------------------------------------------------------
__global__ void __launch_bounds__(128, 2) fused_ffn(
    const float* __restrict__ x,
    const float* __restrict__ theta,
    const float* __restrict__ W1,
    const float* __restrict__ b1,
    const float* __restrict__ W2,
    const float* __restrict__ b2,
    float* __restrict__ out)
{
    extern __shared__ char dsm[];
    char*  sB  = dsm + OFF_B;
    char*  sZ  = dsm + OFF_Z;
    char*  sW1 = dsm + OFF_W1;
    float* b1s = (float*)(dsm + OFF_B1);
    float* b2s = (float*)(dsm + OFF_B2);

    uint32_t sBu  = smem_u32(sB);
    uint32_t sZu  = smem_u32(sZ);
    uint32_t sW1u = smem_u32(sW1);

    int tid = threadIdx.x;
    int e0  = blockIdx.x * NT;
    int gt0 = blockIdx.y * MT;

    // ---------------- Phase 0/1: loads + splits into smem ----------------
    // z: one thread per token row (all 16 q-features)
    {
        const float4* xp = (const float4*)(x + (size_t)(gt0 + tid) * EMBED);
        float4 xv[4];
#pragma unroll
        for (int i = 0; i < 4; i++) xv[i] = xp[i];
        float zf[16];
        const float* xf = (const float*)xv;
#pragma unroll
        for (int j = 0; j < 16; j++)
            zf[j] = __cosf(xf[j]) * __cosf(theta[j]);
        uint32_t hi[8], lo[8];
#pragma unroll
        for (int j = 0; j < 8; j++)
            trunc_split2(zf[2*j], zf[2*j+1], hi[j], lo[j]);
        char* zr = sZ + tid * ZSTRIDE;
        *(uint4*)(zr)      = make_uint4(hi[0], hi[1], hi[2], hi[3]);
        *(uint4*)(zr + 16) = make_uint4(hi[4], hi[5], hi[6], hi[7]);
        *(uint4*)(zr + 32) = make_uint4(lo[0], lo[1], lo[2], lo[3]);
        *(uint4*)(zr + 48) = make_uint4(lo[4], lo[5], lo[6], lo[7]);
    }
    // W1: 2 threads per row (8 floats each)
    {
        int row = tid >> 1, q = tid & 1;
        const float4* wp = (const float4*)(W1 + (size_t)row * NQ + q * 8);
        float4 va = wp[0], vb = wp[1];
        uint32_t h[4], l[4];
        trunc_split2(va.x, va.y, h[0], l[0]);
        trunc_split2(va.z, va.w, h[1], l[1]);
        trunc_split2(vb.x, vb.y, h[2], l[2]);
        trunc_split2(vb.z, vb.w, h[3], l[3]);
        char* rb = sW1 + row * W1STRIDE + q * 16;
        *(uint4*)(rb)      = make_uint4(h[0], h[1], h[2], h[3]);
        *(uint4*)(rb + 32) = make_uint4(l[0], l[1], l[2], l[3]);
    }
    // W2: one thread per row (coalesced), sigma^-1 slot, two 32-float halves
    {
        int wrow = tid;
        int slot = (wrow & ~63) | sigma_inv(wrow & 63);
        char* rb = sB + slot * BSTRIDE;
        const float4* wp = (const float4*)(W2 + (size_t)(e0 + wrow) * FFN);
#pragma unroll
        for (int half = 0; half < 2; half++) {
            float4 v[8];
#pragma unroll
            for (int i = 0; i < 8; i++) v[i] = wp[half * 8 + i];
            uint32_t hi[16], lo[16];
#pragma unroll
            for (int i = 0; i < 8; i++) {
                trunc_split2(v[i].x, v[i].y, hi[2*i],   lo[2*i]);
                trunc_split2(v[i].z, v[i].w, hi[2*i+1], lo[2*i+1]);
            }
            char* dh = rb + half * 64;
            char* dl = rb + 128 + half * 64;
#pragma unroll
            for (int i = 0; i < 4; i++) {
                *(uint4*)(dh + i * 16) = make_uint4(hi[4*i], hi[4*i+1], hi[4*i+2], hi[4*i+3]);
                *(uint4*)(dl + i * 16) = make_uint4(lo[4*i], lo[4*i+1], lo[4*i+2], lo[4*i+3]);
            }
        }
    }
    if (tid < FFN) b1s[tid] = b1[tid];
    b2s[tid] = b2[e0 + tid];
    __syncthreads();

    int wid = tid >> 5, l = tid & 31;
    int wm = wid & 1;        // M block (64 token rows)
    int wn = wid >> 1;       // N block (64 e cols)
    int c  = l & 3;

    // ---------------- Pre-loop: z fragments + output accumulators ----------------
    uint32_t zh[4][4], zl[4][4];
    {
        uint32_t zBase = sZu + (uint32_t)(wm * 64 + (l & 15)) * ZSTRIDE + ((l >> 4) << 4);
#pragma unroll
        for (int mt = 0; mt < 4; mt++) {
            LDSM_X4(zh[mt][0], zh[mt][1], zh[mt][2], zh[mt][3],
                    zBase + (uint32_t)(mt * 16) * ZSTRIDE);
            LDSM_X4(zl[mt][0], zl[mt][1], zl[mt][2], zl[mt][3],
                    zBase + (uint32_t)(mt * 16) * ZSTRIDE + 32);
        }
    }

    float acc[4][8][4];
    {
        int cb = wn * 64;
#pragma unroll
        for (int nt = 0; nt < 8; nt++) {
            int col = cb + 16 * (nt >> 1) + 4 * c + 2 * (nt & 1);
            float bv0 = b2s[col];
            float bv1 = b2s[col + 1];
#pragma unroll
            for (int mt = 0; mt < 4; mt++) {
                acc[mt][nt][0] = bv0; acc[mt][nt][1] = bv1;
                acc[mt][nt][2] = bv0; acc[mt][nt][3] = bv1;
            }
        }
    }

    uint32_t w1Base = sW1u + (uint32_t)((l & 7) + ((l >> 4) << 3)) * W1STRIDE
                           + (((l >> 3) & 1) << 4);
    uint32_t bRow  = (uint32_t)(wn * 64 + (l & 7) + ((l >> 4) << 3));
    uint32_t bBase = sBu + bRow * BSTRIDE + (((l >> 3) & 1) << 4);

    // --- helper: H-chunk MMAs for a given kin -> hacc (bias-initialized) ---
    auto h_mma = [&](int kin, float hacc[4][2][4]) {
        uint32_t w1k = w1Base + (uint32_t)(kin * 16) * W1STRIDE;
        uint32_t w1h[2][2], w1l[2][2];
        {
            uint32_t r0, r1, r2, r3;
            LDSM_X4(r0, r1, r2, r3, w1k);
            w1h[0][0] = r0; w1h[0][1] = r1; w1h[1][0] = r2; w1h[1][1] = r3;
            LDSM_X4(r0, r1, r2, r3, w1k + 32);
            w1l[0][0] = r0; w1l[0][1] = r1; w1l[1][0] = r2; w1l[1][1] = r3;
        }
#pragma unroll
        for (int nt = 0; nt < 2; nt++) {
            int f = kin * 16 + nt * 8 + c * 2;
            float bv0 = b1s[f], bv1 = b1s[f + 1];
#pragma unroll
            for (int mt = 0; mt < 4; mt++) {
                hacc[mt][nt][0] = bv0; hacc[mt][nt][1] = bv1;
                hacc[mt][nt][2] = bv0; hacc[mt][nt][3] = bv1;
            }
        }
#pragma unroll
        for (int mt = 0; mt < 4; mt++)
#pragma unroll
            for (int nt = 0; nt < 2; nt++) {
                MMA16816(hacc[mt][nt], zh[mt][0], zh[mt][1], zh[mt][2], zh[mt][3],
                         w1h[nt][0], w1h[nt][1]);
                MMA16816(hacc[mt][nt], zh[mt][0], zh[mt][1], zh[mt][2], zh[mt][3],
                         w1l[nt][0], w1l[nt][1]);
                MMA16816(hacc[mt][nt], zl[mt][0], zl[mt][1], zl[mt][2], zl[mt][3],
                         w1h[nt][0], w1h[nt][1]);
            }
    };

    auto h_split = [&](float hacc[4][2][4], uint32_t ah[4][4], uint32_t al[4][4]) {
#pragma unroll
        for (int mt = 0; mt < 4; mt++) {
            float v0 = fmaxf(hacc[mt][0][0], 0.0f);
            float v1 = fmaxf(hacc[mt][0][1], 0.0f);
            float v2 = fmaxf(hacc[mt][0][2], 0.0f);
            float v3 = fmaxf(hacc[mt][0][3], 0.0f);
            float v4 = fmaxf(hacc[mt][1][0], 0.0f);
            float v5 = fmaxf(hacc[mt][1][1], 0.0f);
            float v6 = fmaxf(hacc[mt][1][2], 0.0f);
            float v7 = fmaxf(hacc[mt][1][3], 0.0f);
            trunc_split2(v0, v1, ah[mt][0], al[mt][0]);   // rows g,   k0-7
            trunc_split2(v2, v3, ah[mt][1], al[mt][1]);   // rows g+8, k0-7
            trunc_split2(v4, v5, ah[mt][2], al[mt][2]);   // rows g,   k8-15
            trunc_split2(v6, v7, ah[mt][3], al[mt][3]);   // rows g+8, k8-15
        }
    };

    // ---------------- Prologue: H chunk 0 ----------------
    uint32_t ah[4][4], al[4][4];
    {
        float hacc0[4][2][4];
        h_mma(0, hacc0);
        h_split(hacc0, ah, al);
    }

    // ---------------- Main loop: pipelined ----------------
#pragma unroll
    for (int kin = 0; kin < 4; kin++) {
        uint32_t kb = (uint32_t)(kin * 32);

        uint32_t bh[8][2];
#pragma unroll
        for (int j = 0; j < 4; j++) {
            uint32_t r0, r1, r2, r3;
            LDSM_X4(r0, r1, r2, r3, bBase + (uint32_t)(j * 16) * BSTRIDE + kb);
            bh[2*j][0] = r0;  bh[2*j][1] = r1;
            bh[2*j+1][0] = r2; bh[2*j+1][1] = r3;
        }

        // term 0: Hh * Wh
#pragma unroll
        for (int mt = 0; mt < 4; mt++)
#pragma unroll
            for (int nt = 0; nt < 8; nt++)
                MMA16816(acc[mt][nt], ah[mt][0], ah[mt][1], ah[mt][2], ah[mt][3],
                         bh[nt][0], bh[nt][1]);

        // H chunk for kin+1 — independent of acc chain; overlaps with t2/t1
        float haccN[4][2][4];
        if (kin < 3) h_mma(kin + 1, haccN);

        // term 2: Hl * Wh
#pragma unroll
        for (int mt = 0; mt < 4; mt++)
#pragma unroll
            for (int nt = 0; nt < 8; nt++)
                MMA16816(acc[mt][nt], al[mt][0], al[mt][1], al[mt][2], al[mt][3],
                         bh[nt][0], bh[nt][1]);

        uint32_t bl[8][2];
#pragma unroll
        for (int j = 0; j < 4; j++) {
            uint32_t r0, r1, r2, r3;
            LDSM_X4(r0, r1, r2, r3, bBase + (uint32_t)(j * 16) * BSTRIDE + 128 + kb);
            bl[2*j][0] = r0;  bl[2*j][1] = r1;
            bl[2*j+1][0] = r2; bl[2*j+1][1] = r3;
        }

        // term 1: Hh * Wl
#pragma unroll
        for (int mt = 0; mt < 4; mt++)
#pragma unroll
            for (int nt = 0; nt < 8; nt++)
                MMA16816(acc[mt][nt], ah[mt][0], ah[mt][1], ah[mt][2], ah[mt][3],
                         bl[nt][0], bl[nt][1]);

        // split for next iteration (after ah/al are dead)
        if (kin < 3) h_split(haccN, ah, al);
    }

    // ---------------- Epilogue: sigma layout -> contiguous float4 ----------------
    {
        int row_l = l >> 2;
#pragma unroll
        for (int mt = 0; mt < 4; mt++) {
            int r0 = gt0 + wm * 64 + mt * 16 + row_l;
            float* base0 = out + (size_t)r0 * EMBED + e0 + wn * 64;
            float* base1 = base0 + (size_t)8 * EMBED;
#pragma unroll
            for (int g = 0; g < 4; g++) {
                float4 v0, v1;
                v0.x = acc[mt][2*g][0];   v0.y = acc[mt][2*g][1];
                v0.z = acc[mt][2*g+1][0]; v0.w = acc[mt][2*g+1][1];
                v1.x = acc[mt][2*g][2];   v1.y = acc[mt][2*g][3];
                v1.z = acc[mt][2*g+1][2]; v1.w = acc[mt][2*g+1][3];
                *(float4*)(base0 + 16 * g + 4 * c) = v0;
                *(float4*)(base1 + 16 * g + 4 * c) = v1;
            }
        }
    }
}

// ---------------------------------------------------------------------------
extern "C" void kernel_launch(void* const* d_in, const int* in_sizes, int n_in,
                              void* d_out, int out_size)
{
    const float *x = nullptr, *theta = nullptr, *W1 = nullptr,
                *b1 = nullptr, *W2 = nullptr, *b2 = nullptr;
    for (int i = 0; i < n_in; i++) {
        switch (in_sizes[i]) {
            case NTOK * EMBED: x     = (const float*)d_in[i]; break;
            case NQ:           theta = (const float*)d_in[i]; break;
            case FFN * NQ:     W1    = (const float*)d_in[i]; break;
            case FFN:          b1    = (const float*)d_in[i]; break;
            case EMBED * FFN:  W2    = (const float*)d_in[i]; break;
            case EMBED:        b2    = (const float*)d_in[i]; break;
            default: break;
        }
    }
    float* out = (float*)d_out;

    static int smem_set = 0;
    if (!smem_set) {
        cudaFuncSetAttribute(fused_ffn,
                             cudaFuncAttributeMaxDynamicSharedMemorySize,
                             SMEM_TOTAL);
        smem_set = 1;
    }

    fused_ffn<<<dim3(EMBED / NT, NTOK / MT), 128, SMEM_TOTAL>>>(
        x, theta, W1, b1, W2, b2, out);
}